// round 16
// baseline (speedup 1.0000x reference)
#include <cuda_runtime.h>
#include <cuda_fp16.h>
#include <cuda_bf16.h>
#include <cstdint>

// ---------------------------------------------------------------------------
// Problem constants
// ---------------------------------------------------------------------------
#define B_  256
#define T_  512
#define I_  300
#define H_  64
#define G3  192          // 3*H
#define NCAT 384         // 6*H
#define KP  320          // K padded (5 tiles of 64)
#define M_  (B_ * T_)    // 131072

#define BM 128
#define BN 128
#define BK 64
#define KTILES (KP / BK) // 5
#define NBLK (NCAT / BN) // 3
#define NITER (NBLK * KTILES) // 15

// gemm smem layout (bytes): sA[5] slabs (16KB each) | sB double (2 x 16KB)
#define SLAB  16384
#define OF_B  (5 * SLAB)          // 81920
#define GSMEM (7 * SLAB)          // 114688

// Scratch (static device memory; no allocation allowed)
__device__ float g_xp[(size_t)M_ * NCAT];         // ~201 MB
__device__ __half g_W1[NCAT * KP];                // W fp16, [n][k] K-major, padded
__device__ float g_bcat[NCAT];
__device__ float g_feat[B_ * 256];                // [b][ hf1 | hbF | hfF | hb1 ]

// ---------------------------------------------------------------------------
// MMA / ldmatrix / cp.async helpers (baseline PTX, legal on sm_103)
// ---------------------------------------------------------------------------
__device__ __forceinline__ uint32_t smem_u32(const void* p) {
    uint32_t a;
    asm("{ .reg .u64 t; cvta.to.shared.u64 t, %1; cvt.u32.u64 %0, t; }"
        : "=r"(a) : "l"(p));
    return a;
}
__device__ __forceinline__ void ldsm_x4(uint32_t addr, uint32_t& r0, uint32_t& r1,
                                        uint32_t& r2, uint32_t& r3) {
    asm volatile("ldmatrix.sync.aligned.m8n8.x4.shared.b16 {%0,%1,%2,%3}, [%4];"
                 : "=r"(r0), "=r"(r1), "=r"(r2), "=r"(r3) : "r"(addr));
}
__device__ __forceinline__ void mma16816h(float* d, const uint32_t* a,
                                          uint32_t b0, uint32_t b1) {
    asm volatile(
        "mma.sync.aligned.m16n8k16.row.col.f32.f16.f16.f32 "
        "{%0,%1,%2,%3}, {%4,%5,%6,%7}, {%8,%9}, {%0,%1,%2,%3};"
        : "+f"(d[0]), "+f"(d[1]), "+f"(d[2]), "+f"(d[3])
        : "r"(a[0]), "r"(a[1]), "r"(a[2]), "r"(a[3]), "r"(b0), "r"(b1));
}
__device__ __forceinline__ void cp_async16(uint32_t dst, const void* src) {
    asm volatile("cp.async.cg.shared.global [%0], [%1], 16;"
                 :: "r"(dst), "l"(src) : "memory");
}
__device__ __forceinline__ void cp_commit() {
    asm volatile("cp.async.commit_group;" ::: "memory");
}
__device__ __forceinline__ void cp_wait0() {
    asm volatile("cp.async.wait_group 0;" ::: "memory");
}

// swizzled byte offset within a [rows][64 fp16] tile (128B rows, SW128-style)
__device__ __forceinline__ uint32_t swzB(int r, int u) {
    return (uint32_t)(r * 128 + ((u ^ (r & 7)) << 4));
}

// ---------------------------------------------------------------------------
// f32x2 packed helpers (for scan)
// ---------------------------------------------------------------------------
__device__ __forceinline__ unsigned long long pack2(float lo, float hi) {
    unsigned long long r;
    asm("mov.b64 %0, {%1, %2};" : "=l"(r) : "f"(lo), "f"(hi));
    return r;
}
__device__ __forceinline__ unsigned long long fma2(unsigned long long a,
                                                   unsigned long long b,
                                                   unsigned long long c) {
    unsigned long long d;
    asm("fma.rn.f32x2 %0, %1, %2, %3;" : "=l"(d) : "l"(a), "l"(b), "l"(c));
    return d;
}
__device__ __forceinline__ float2 unpack2(unsigned long long v) {
    float lo, hi;
    asm("mov.b64 {%0, %1}, %2;" : "=f"(lo), "=f"(hi) : "l"(v));
    return make_float2(lo, hi);
}
__device__ __forceinline__ float sigmoidf_(float x) {
    return __fdividef(1.f, 1.f + __expf(-x));
}
__device__ __forceinline__ float tanhf_(float x) {
    return 1.f - __fdividef(2.f, 1.f + __expf(2.f * x));
}

// ---------------------------------------------------------------------------
// Dummy kernel: keeps the profiler's 4th-launch capture on scan_kernel
// ---------------------------------------------------------------------------
__global__ void dummyA_kernel() {}

// ---------------------------------------------------------------------------
// Kernel 0: build fp16 combined weight + fp32 bias
// ---------------------------------------------------------------------------
__global__ void prep_kernel(const float* __restrict__ Wif,
                            const float* __restrict__ Wib,
                            const float* __restrict__ bif,
                            const float* __restrict__ bib) {
    int i = blockIdx.x * blockDim.x + threadIdx.x;
    if (i < NCAT) g_bcat[i] = (i < G3) ? bif[i] : bib[i - G3];
    if (i < NCAT * KP) {
        int n = i / KP, k = i % KP;
        float v = 0.f;
        if (k < I_) v = (n < G3) ? Wif[n * I_ + k] : Wib[(n - G3) * I_ + k];
        g_W1[i] = __float2half_rn(v);
    }
}

// ---------------------------------------------------------------------------
// Kernel 1: HMMA fp16 GEMM with smem-resident A (R15-exact, proven 178us)
// ---------------------------------------------------------------------------
__global__ __launch_bounds__(512) void gemm_mma(const float* __restrict__ A) {
    extern __shared__ __align__(128) char smem[];

    const int tid = threadIdx.x;
    const int wid = tid >> 5;
    const int lid = tid & 31;
    const int m0 = blockIdx.x * BM;

    const int wm = wid & 3;          // M quarter -> rows wm*32
    const int wn = wid >> 2;         // N quarter -> cols wn*32

    const int ar = tid >> 2;
    const int acb = (tid & 3) * 16;
    const float* Arow = A + (size_t)(m0 + ar) * I_;

    const int br = tid >> 2;
    const int bu = (tid & 3) * 2;
    const __half* Bbase = g_W1 + (size_t)br * KP;

    float4 va[4];

    {
#pragma unroll
        for (int j = 0; j < 2; j++)
            cp_async16(smem_u32(smem + OF_B) + swzB(br, bu + j),
                       Bbase + (bu + j) * 8);
        cp_commit();
#pragma unroll
        for (int j = 0; j < 4; j++) {
            int c = acb + j * 4;
            va[j] = (c < I_) ? *(const float4*)(Arow + c)
                             : make_float4(0.f, 0.f, 0.f, 0.f);
        }
    }

    float acc[2][4][4];
#pragma unroll
    for (int i = 0; i < 2; i++)
#pragma unroll
        for (int j = 0; j < 4; j++)
#pragma unroll
            for (int q = 0; q < 4; q++) acc[i][j][q] = 0.f;

    const int rA = lid & 15;
    const int uhalf = lid >> 4;
    const int erow = lid >> 2;
    const int ecol = (lid & 3) * 2;

    for (int it = 0; it < NITER; it++) {
        const int t = it % KTILES;
        char* sAt = smem + t * SLAB;

        if (it < KTILES) {
#pragma unroll
            for (int m = 0; m < 2; m++) {
                float f[8] = {va[2 * m].x, va[2 * m].y, va[2 * m].z,
                              va[2 * m].w, va[2 * m + 1].x, va[2 * m + 1].y,
                              va[2 * m + 1].z, va[2 * m + 1].w};
                uint32_t hp[4];
#pragma unroll
                for (int q = 0; q < 4; q++) {
                    __half2 hh = __halves2half2(__float2half_rn(f[2 * q]),
                                                __float2half_rn(f[2 * q + 1]));
                    hp[q] = *(uint32_t*)&hh;
                }
                uint32_t off = swzB(ar, (acb >> 3) + m);
                *(uint4*)(sAt + off) = make_uint4(hp[0], hp[1], hp[2], hp[3]);
            }
        }

        cp_wait0();
        __syncthreads();

        if (it + 1 < NITER) {
            const int tn = (it + 1) % KTILES;
            const int nn = (it + 1) / KTILES;
            char* sBn = smem + OF_B + ((it + 1) & 1) * SLAB;
            const __half* Bn = Bbase + (size_t)(nn * BN) * KP + tn * BK;
#pragma unroll
            for (int j = 0; j < 2; j++)
                cp_async16(smem_u32(sBn) + swzB(br, bu + j), Bn + (bu + j) * 8);
            cp_commit();
            if (it + 1 < KTILES) {
                const int k0 = (it + 1) * BK;
#pragma unroll
                for (int j = 0; j < 4; j++) {
                    int c = k0 + acb + j * 4;
                    va[j] = (c < I_) ? *(const float4*)(Arow + c)
                                     : make_float4(0.f, 0.f, 0.f, 0.f);
                }
            }
        }

        const uint32_t a1B = smem_u32(sAt);
        const uint32_t b1B = smem_u32(smem + OF_B + (it & 1) * SLAB);
#pragma unroll
        for (int s = 0; s < 4; s++) {
            uint32_t af1[2][4], bf1[2][4];
            const int uu = s * 2 + uhalf;
#pragma unroll
            for (int i = 0; i < 2; i++) {
                uint32_t o = swzB(wm * 32 + i * 16 + rA, uu);
                ldsm_x4(a1B + o, af1[i][0], af1[i][1], af1[i][2], af1[i][3]);
            }
#pragma unroll
            for (int j2 = 0; j2 < 2; j2++) {
                uint32_t o = swzB(wn * 32 + j2 * 16 + rA, uu);
                ldsm_x4(b1B + o, bf1[j2][0], bf1[j2][1], bf1[j2][2], bf1[j2][3]);
            }
#pragma unroll
            for (int i = 0; i < 2; i++) {
#pragma unroll
                for (int j2 = 0; j2 < 2; j2++) {
#pragma unroll
                    for (int g = 0; g < 2; g++) {
                        int j = j2 * 2 + g;
                        mma16816h(acc[i][j], af1[i], bf1[j2][g], bf1[j2][g + 2]);
                    }
                }
            }
        }

        if (t == KTILES - 1) {
            const int n0 = (it / KTILES) * BN;
#pragma unroll
            for (int i = 0; i < 2; i++) {
                int grow = m0 + wm * 32 + i * 16 + erow;
                float* out0 = g_xp + (size_t)grow * NCAT;
                float* out1 = g_xp + (size_t)(grow + 8) * NCAT;
#pragma unroll
                for (int j = 0; j < 4; j++) {
                    int gcol = n0 + wn * 32 + j * 8 + ecol;
                    float2 bi = *(const float2*)(g_bcat + gcol);
                    *(float2*)(out0 + gcol) =
                        make_float2(acc[i][j][0] + bi.x, acc[i][j][1] + bi.y);
                    *(float2*)(out1 + gcol) =
                        make_float2(acc[i][j][2] + bi.x, acc[i][j][3] + bi.y);
                    acc[i][j][0] = 0.f; acc[i][j][1] = 0.f;
                    acc[i][j][2] = 0.f; acc[i][j][3] = 0.f;
                }
            }
        }
    }
}

// ---------------------------------------------------------------------------
// Kernel 2: bidirectional GRU scan — TWO batches per thread, shared weights.
//   Grid 128 = batch-pair; block 128 threads: pair = tid>>6 (0=fwd, 1=bwd),
//   u = tid&63. Thread serves unit u of chains (2bx, dir) and (2bx+1, dir)
//   with ONE set of 96 f32x2 weight regs (same dir => same W_hh).
//   Back-to-back dots give intra-warp ILP; ONE barrier per superstep
//   (= one time step of both chains). Warp pairs land on SMSP {0,1},{2,3}.
// ---------------------------------------------------------------------------
__global__ __launch_bounds__(128) void scan_kernel(
    const float* __restrict__ Whhf, const float* __restrict__ Whhb,
    const float* __restrict__ bhhf, const float* __restrict__ bhhb) {
    __shared__ __align__(16) float hbuf[2][2][2][H_]; // [pair][chain][parity][u]

    const int bx = blockIdx.x;
    const int tid = threadIdx.x;
    const int pair = tid >> 6;           // == dir
    const int u = tid & 63;
    const int dir = pair;
    const int b0 = bx * 2, b1 = bx * 2 + 1;

    const float* Whh = dir ? Whhb : Whhf;
    const float* bhh = dir ? bhhb : bhhf;

    unsigned long long wr[32], wz[32], wn_[32];
    {
        const float2* r0 = (const float2*)(Whh + (size_t)u * H_);
        const float2* r1 = (const float2*)(Whh + (size_t)(64 + u) * H_);
        const float2* r2 = (const float2*)(Whh + (size_t)(128 + u) * H_);
#pragma unroll
        for (int k = 0; k < 32; k++) {
            float2 a = r0[k], c = r1[k], d = r2[k];
            wr[k] = pack2(a.x, a.y);
            wz[k] = pack2(c.x, c.y);
            wn_[k] = pack2(d.x, d.y);
        }
    }
    const float br_ = bhh[u];
    const float bz_ = bhh[64 + u];
    const float bn_ = bhh[128 + u];

    hbuf[pair][0][0][u] = 0.f;
    hbuf[pair][1][0][u] = 0.f;
    float hregA = 0.f, hregB = 0.f;

    const int stp = dir ? -NCAT : NCAT;
    const size_t dofs = (dir ? (size_t)(T_ - 1) * NCAT : 0) + dir * G3 + u;
    const float* pA = g_xp + (size_t)b0 * (T_ * NCAT) + dofs;
    const float* pB = g_xp + (size_t)b1 * (T_ * NCAT) + dofs;

    float xrA0 = pA[0], xzA0 = pA[64], xnA0 = pA[128];
    float xrB0 = pB[0], xzB0 = pB[64], xnB0 = pB[128];
    pA += stp; pB += stp;
    float xrA1 = pA[0], xzA1 = pA[64], xnA1 = pA[128];
    float xrB1 = pB[0], xzB1 = pB[64], xnB1 = pB[128];
    pA += stp; pB += stp;
    __syncthreads();

    for (int s = 0; s < T_; s++) {
        // ---- chain A dot + update ----
        {
            const ulonglong2* hp = (const ulonglong2*)hbuf[pair][0][s & 1];
            unsigned long long ar0 = pack2(br_, 0.f), ar1 = pack2(0.f, 0.f);
            unsigned long long az0 = pack2(bz_, 0.f), az1 = pack2(0.f, 0.f);
            unsigned long long an0 = pack2(bn_, 0.f), an1 = pack2(0.f, 0.f);
#pragma unroll
            for (int k = 0; k < 16; k++) {
                ulonglong2 hv = hp[k];
                ar0 = fma2(wr[2 * k], hv.x, ar0);
                ar1 = fma2(wr[2 * k + 1], hv.y, ar1);
                az0 = fma2(wz[2 * k], hv.x, az0);
                az1 = fma2(wz[2 * k + 1], hv.y, az1);
                an0 = fma2(wn_[2 * k], hv.x, an0);
                an1 = fma2(wn_[2 * k + 1], hv.y, an1);
            }
            float2 pr0 = unpack2(ar0), pr1 = unpack2(ar1);
            float2 pz0 = unpack2(az0), pz1 = unpack2(az1);
            float2 pn0 = unpack2(an0), pn1 = unpack2(an1);
            float hr = (pr0.x + pr0.y) + (pr1.x + pr1.y);
            float hz = (pz0.x + pz0.y) + (pz1.x + pz1.y);
            float hn = (pn0.x + pn0.y) + (pn1.x + pn1.y);
            float r = sigmoidf_(xrA0 + hr);
            float z = sigmoidf_(xzA0 + hz);
            float n = tanhf_(xnA0 + r * hn);
            hregA = fmaf(z, hregA - n, n);
            hbuf[pair][0][(s + 1) & 1][u] = hregA;
        }
        // ---- chain B dot + update ----
        {
            const ulonglong2* hp = (const ulonglong2*)hbuf[pair][1][s & 1];
            unsigned long long ar0 = pack2(br_, 0.f), ar1 = pack2(0.f, 0.f);
            unsigned long long az0 = pack2(bz_, 0.f), az1 = pack2(0.f, 0.f);
            unsigned long long an0 = pack2(bn_, 0.f), an1 = pack2(0.f, 0.f);
#pragma unroll
            for (int k = 0; k < 16; k++) {
                ulonglong2 hv = hp[k];
                ar0 = fma2(wr[2 * k], hv.x, ar0);
                ar1 = fma2(wr[2 * k + 1], hv.y, ar1);
                az0 = fma2(wz[2 * k], hv.x, az0);
                az1 = fma2(wz[2 * k + 1], hv.y, az1);
                an0 = fma2(wn_[2 * k], hv.x, an0);
                an1 = fma2(wn_[2 * k + 1], hv.y, an1);
            }
            float2 pr0 = unpack2(ar0), pr1 = unpack2(ar1);
            float2 pz0 = unpack2(az0), pz1 = unpack2(az1);
            float2 pn0 = unpack2(an0), pn1 = unpack2(an1);
            float hr = (pr0.x + pr0.y) + (pr1.x + pr1.y);
            float hz = (pz0.x + pz0.y) + (pz1.x + pz1.y);
            float hn = (pn0.x + pn0.y) + (pn1.x + pn1.y);
            float r = sigmoidf_(xrB0 + hr);
            float z = sigmoidf_(xzB0 + hz);
            float n = tanhf_(xnB0 + r * hn);
            hregB = fmaf(z, hregB - n, n);
            hbuf[pair][1][(s + 1) & 1][u] = hregB;
        }

        if (s == 0) {
            g_feat[b0 * 256 + (dir ? 192 : 0) + u] = hregA;
            g_feat[b1 * 256 + (dir ? 192 : 0) + u] = hregB;
        }
        if (s == T_ - 1) {
            g_feat[b0 * 256 + (dir ? 64 : 128) + u] = hregA;
            g_feat[b1 * 256 + (dir ? 64 : 128) + u] = hregB;
        }

        xrA0 = xrA1; xzA0 = xzA1; xnA0 = xnA1;
        xrB0 = xrB1; xzB0 = xzB1; xnB0 = xnB1;
        if (s + 2 < T_) {
            xrA1 = pA[0]; xzA1 = pA[64]; xnA1 = pA[128];
            xrB1 = pB[0]; xzB1 = pB[64]; xnB1 = pB[128];
        }
        pA += stp; pB += stp;
        __syncthreads();
    }
}

// ---------------------------------------------------------------------------
// Kernel 3: head MLP  feat[256] -> 32 (LeakyReLU) -> 1
// ---------------------------------------------------------------------------
__global__ __launch_bounds__(256) void head_kernel(
    const float* __restrict__ W1, const float* __restrict__ b1,
    const float* __restrict__ W2, const float* __restrict__ b2,
    float* __restrict__ out) {
    __shared__ float fs[256];
    __shared__ float hs[32];
    const int b = blockIdx.x;
    const int tid = threadIdx.x;
    fs[tid] = g_feat[b * 256 + tid];
    __syncthreads();

    const int j = tid >> 3, p = tid & 7;
    const float* w = W1 + j * 256 + p * 32;
    const float* f = fs + p * 32;
    float acc = 0.f;
#pragma unroll
    for (int i = 0; i < 32; i++) acc = fmaf(f[i], w[i], acc);
    acc += __shfl_xor_sync(0xffffffffu, acc, 1);
    acc += __shfl_xor_sync(0xffffffffu, acc, 2);
    acc += __shfl_xor_sync(0xffffffffu, acc, 4);
    if (p == 0) {
        float hv = acc + b1[j];
        hv = (hv >= 0.f) ? hv : 0.01f * hv;
        hs[j] = hv * W2[j];
    }
    __syncthreads();
    if (tid < 32) {
        float v = hs[tid];
#pragma unroll
        for (int o = 16; o > 0; o >>= 1) v += __shfl_xor_sync(0xffffffffu, v, o);
        if (tid == 0) out[b] = v + b2[0];
    }
}

// ---------------------------------------------------------------------------
extern "C" void kernel_launch(void* const* d_in, const int* in_sizes, int n_in,
                              void* d_out, int out_size) {
    const float* x    = (const float*)d_in[0];
    const float* Wif  = (const float*)d_in[1];
    const float* Whhf = (const float*)d_in[2];
    const float* bif  = (const float*)d_in[3];
    const float* bhhf = (const float*)d_in[4];
    const float* Wib  = (const float*)d_in[5];
    const float* Whhb = (const float*)d_in[6];
    const float* bib  = (const float*)d_in[7];
    const float* bhhb = (const float*)d_in[8];
    const float* W1   = (const float*)d_in[9];
    const float* b1   = (const float*)d_in[10];
    const float* W2   = (const float*)d_in[11];
    const float* b2   = (const float*)d_in[12];
    float* out = (float*)d_out;

    cudaFuncSetAttribute(gemm_mma, cudaFuncAttributeMaxDynamicSharedMemorySize,
                         GSMEM);

    prep_kernel<<<(NCAT * KP + 255) / 256, 256>>>(Wif, Wib, bif, bib);

    gemm_mma<<<M_ / BM, 512, GSMEM>>>(x);

    dummyA_kernel<<<1, 32>>>();

    scan_kernel<<<B_ / 2, 128>>>(Whhf, Whhb, bhhf, bhhb);  // 4th -> ncu

    head_kernel<<<B_, 256>>>(W1, b1, W2, b2, out);
}